// round 15
// baseline (speedup 1.0000x reference)
#include <cuda_runtime.h>
#include <cuda_fp16.h>
#include <cstdint>

// ---------------- problem constants ----------------
#define BB      16
#define C_OUTX  128
#define C_INX   256
#define N_LOW   10242
#define N_UP    40962
#define KNEIGH  7
#define KF      896               // KNEIGH * C_OUTX
#define NFLAT   (N_LOW * KNEIGH)  // 71694
#define TM      128
#define NTH     256
#define VTILES  81
#define NTILES  (VTILES * BB)     // 1296
#define GBLK    ((N_UP + 31) / 32)    // 1281
#define NGATHER (GBLK * BB)           // 20496
#define NT_TOTAL (NTILES + NGATHER)   // 21792
#define NCSR    16

// ---------------- SMEM layout ----------------
#define A_OFF    0
#define A_STRIDE 528
#define A_BYTES  (128 * A_STRIDE)       // 67584
#define B_OFF    A_BYTES
#define B_STRIDE 144
#define B_BUF    (128 * B_STRIDE)       // 18432
#define BIAS_OFF (B_OFF + 2 * B_BUF)    // 104448
#define SMEM_ALLOC (BIAS_OFF + KF * 4)  // 108032

#define SCAN_NB  ((N_UP + 255) / 256)   // 161

// ---------------- device scratch ----------------
__device__ int   g_cnt[N_UP];
__device__ int   g_off[N_UP + 1];
__device__ int   g_pos[N_UP];
__device__ int   g_csr[NFLAT];
__device__ float g_inv[N_UP];
__device__ int   g_bsum[SCAN_NB];
__device__ int   g_bbase[SCAN_NB];
__device__ __half g_wpack[KNEIGH * 4 * 128 * 64];
__device__ __half g_y[(size_t)NFLAT * BB * C_OUTX];
// scheduling state (reset each launch by reset_k)
__device__ unsigned int g_ticket;
__device__ int g_done[BB];
__device__ unsigned int g_cbar;
__device__ int g_ready;

// ---------------- PTX helpers (plain sm_80+) ----------------
__device__ __forceinline__ uint32_t smem_u32(const void* p) {
    uint32_t a;
    asm("{ .reg .u64 t; cvta.to.shared.u64 t, %1; cvt.u32.u64 %0, t; }" : "=r"(a) : "l"(p));
    return a;
}
#define LDSM4(r, addr) \
    asm volatile("ldmatrix.sync.aligned.m8n8.x4.shared.b16 {%0,%1,%2,%3}, [%4];" \
        : "=r"((r)[0]), "=r"((r)[1]), "=r"((r)[2]), "=r"((r)[3]) : "r"(addr))
#define MMA16816(d, a, b0, b1) \
    asm volatile("mma.sync.aligned.m16n8k16.row.col.f32.f16.f16.f32 " \
        "{%0,%1,%2,%3}, {%4,%5,%6,%7}, {%8,%9}, {%0,%1,%2,%3};" \
        : "+f"((d)[0]), "+f"((d)[1]), "+f"((d)[2]), "+f"((d)[3]) \
        : "r"((a)[0]), "r"((a)[1]), "r"((a)[2]), "r"((a)[3]), "r"(b0), "r"(b1))
#define CP16(dst, src) \
    asm volatile("cp.async.cg.shared.global [%0], [%1], 16;" :: "r"(dst), "l"(src))
#define CP_COMMIT() asm volatile("cp.async.commit_group;")
#define CP_WAIT0()  asm volatile("cp.async.wait_group 0;")

__device__ __forceinline__ uint32_t h2pack(float a, float b) {
    __half2 h = __floats2half2_rn(a, b);
    return *(uint32_t*)&h;
}

// ---------------- small prep kernels ----------------
__global__ void reset_k() {
    if (threadIdx.x == 0) { g_ticket = 0; g_cbar = 0; g_ready = 0; }
    if (threadIdx.x < BB) g_done[threadIdx.x] = 0;
}
__global__ void prep_w_k(const float* __restrict__ w) {
    int idx = blockIdx.x * blockDim.x + threadIdx.x;
    if (idx >= KNEIGH * 4 * 128 * 64) return;
    int kk = idx & 63;
    int n  = (idx >> 6) & 127;
    int c  = (idx >> 13) & 3;
    int kg = idx >> 15;
    float v = w[(size_t)(c * 64 + kk) * KF + kg * C_OUTX + n];
    g_wpack[(size_t)(kg * 4 + c) * 8192 + n * 64 + kk] = __float2half_rn(v);
}

// ---------------- mega-kernel pieces ----------------
__device__ __forceinline__ void csr_bar(int gen) {
    __syncthreads();
    __threadfence();
    if (threadIdx.x == 0) {
        atomicAdd(&g_cbar, 1u);
        while ((int)atomicAdd(&g_cbar, 0u) < gen * NCSR) __nanosleep(128);
    }
    __syncthreads();
}

__device__ void csr_build(const int* __restrict__ neigh, int cix) {
    const int tid = threadIdx.x;
    __shared__ int wsS[8];
    for (int i = cix * NTH + tid; i < N_UP; i += NCSR * NTH) { g_cnt[i] = 0; g_pos[i] = 0; }
    csr_bar(1);
    for (int i = cix * NTH + tid; i < NFLAT; i += NCSR * NTH) atomicAdd(&g_cnt[neigh[i]], 1);
    csr_bar(2);
    for (int cb = cix; cb < SCAN_NB; cb += NCSR) {
        int i = cb * 256 + tid;
        int v = (i < N_UP) ? g_cnt[i] : 0;
        int r = v;
#pragma unroll
        for (int d = 16; d > 0; d >>= 1) r += __shfl_down_sync(0xFFFFFFFFu, r, d);
        if ((tid & 31) == 0) wsS[tid >> 5] = r;
        __syncthreads();
        if (tid == 0) {
            int s = 0;
#pragma unroll
            for (int j = 0; j < 8; ++j) s += wsS[j];
            g_bsum[cb] = s;
        }
        __syncthreads();
    }
    csr_bar(3);
    if (cix == 0) {
        int v = (tid < SCAN_NB) ? g_bsum[tid] : 0;
        int s = v;
#pragma unroll
        for (int d = 1; d < 32; d <<= 1) {
            int t = __shfl_up_sync(0xFFFFFFFFu, s, d);
            if ((tid & 31) >= d) s += t;
        }
        if ((tid & 31) == 31) wsS[tid >> 5] = s;
        __syncthreads();
        if (tid < 32) {
            int w = (tid < 8) ? wsS[tid] : 0;
#pragma unroll
            for (int d = 1; d < 8; d <<= 1) {
                int t = __shfl_up_sync(0xFFFFFFFFu, w, d);
                if (tid >= d) w += t;
            }
            if (tid < 8) wsS[tid] = w;
        }
        __syncthreads();
        int incl = s + ((tid >= 32) ? wsS[(tid >> 5) - 1] : 0);
        if (tid < SCAN_NB) g_bbase[tid] = incl - v;
        if (tid == 0) g_off[N_UP] = NFLAT;
        __syncthreads();
    }
    csr_bar(4);
    for (int cb = cix; cb < SCAN_NB; cb += NCSR) {
        int i = cb * 256 + tid;
        int v = (i < N_UP) ? g_cnt[i] : 0;
        int s = v;
#pragma unroll
        for (int d = 1; d < 32; d <<= 1) {
            int t = __shfl_up_sync(0xFFFFFFFFu, s, d);
            if ((tid & 31) >= d) s += t;
        }
        if ((tid & 31) == 31) wsS[tid >> 5] = s;
        __syncthreads();
        if (tid < 32) {
            int w = (tid < 8) ? wsS[tid] : 0;
#pragma unroll
            for (int d = 1; d < 8; d <<= 1) {
                int t = __shfl_up_sync(0xFFFFFFFFu, w, d);
                if (tid >= d) w += t;
            }
            if (tid < 8) wsS[tid] = w;
        }
        __syncthreads();
        int excl = s - v + ((tid >= 32) ? wsS[(tid >> 5) - 1] : 0);
        if (i < N_UP) {
            g_off[i] = g_bbase[cb] + excl;
            g_inv[i] = 1.0f / (float)v;
        }
        __syncthreads();
    }
    csr_bar(5);
    for (int i = cix * NTH + tid; i < NFLAT; i += NCSR * NTH) {
        int u = neigh[i];
        int slot = atomicAdd(&g_pos[u], 1);
        g_csr[g_off[u] + slot] = i;
    }
    csr_bar(6);
    if (cix == 0 && tid == 0) atomicExch(&g_ready, 1);
}

__device__ __forceinline__ void issue_chunk(uint32_t sb, int tid, int t, int buf) {
    const __half* src = g_wpack + (size_t)t * 8192;
    uint32_t dst = sb + B_OFF + buf * B_BUF;
#pragma unroll
    for (int o = 0; o < 4; ++o) {
        int flat = o * NTH + tid;
        int n   = flat >> 3;
        int seg = flat & 7;
        CP16(dst + n * B_STRIDE + seg * 16, (const char*)src + n * 128 + seg * 16);
    }
}

// one GEMM tile: 128 vertices x one batch, all 7 neighbor groups
__device__ void do_tile(int job, const float* __restrict__ x, char* sm, uint32_t sb) {
    const int tid    = threadIdx.x;
    const int wid    = tid >> 5;
    const int lane   = tid & 31;
    const int warp_m = wid & 3;
    const int warp_n = wid >> 2;
    const int v0     = (job % VTILES) * TM;
    const int b      = job / VTILES;

    {
        const float* xb = x + (size_t)b * C_INX * N_LOW;
        const int v = tid & 127;
        const int cs = (tid >> 7) * 2;
        const bool valid = (v0 + v) < N_LOW;
        for (int c = cs; c < C_INX; c += 4) {
            float f0 = valid ? __ldcs(xb + (size_t)c * N_LOW + v0 + v) : 0.0f;
            float f1 = valid ? __ldcs(xb + (size_t)(c + 1) * N_LOW + v0 + v) : 0.0f;
            *(__half2*)(sm + A_OFF + v * A_STRIDE + c * 2) = __floats2half2_rn(f0, f1);
        }
    }
    issue_chunk(sb, tid, 0, 0);
    CP_COMMIT();

    const uint32_t aB = sb + A_OFF + (warp_m * 32 + (lane & 15)) * A_STRIDE + (lane >> 4) * 16;
    const uint32_t brOff = (uint32_t)(warp_n * 64 + (lane & 7) + ((lane >> 4) & 1) * 8) * B_STRIDE
                         + ((lane >> 3) & 1) * 16;

    float acc[2][8][4];
#pragma unroll
    for (int mi = 0; mi < 2; ++mi)
#pragma unroll
        for (int ni = 0; ni < 8; ++ni)
#pragma unroll
            for (int q = 0; q < 4; ++q) acc[mi][ni][q] = 0.0f;

    const int qq = lane & 3;
    const int rr = lane >> 2;

    for (int kg = 0; kg < KNEIGH; ++kg) {
#pragma unroll
        for (int c = 0; c < 4; ++c) {
            const int t = kg * 4 + c;
            CP_WAIT0();
            __syncthreads();
            if (t + 1 < 28) { issue_chunk(sb, tid, t + 1, (t + 1) & 1); CP_COMMIT(); }

            const uint32_t bB = sb + B_OFF + (t & 1) * B_BUF + brOff;
            const int cByte = c * 128;
#pragma unroll
            for (int s = 0; s < 4; ++s) {
                const int kb = cByte + s * 32;
                uint32_t af[2][4], bf[4][4];
                LDSM4(af[0], aB + kb);
                LDSM4(af[1], aB + 16 * A_STRIDE + kb);
#pragma unroll
                for (int p = 0; p < 4; ++p)
                    LDSM4(bf[p], bB + p * (16 * B_STRIDE) + s * 32);
#pragma unroll
                for (int ni = 0; ni < 8; ++ni) {
                    const uint32_t b0r = bf[ni >> 1][(ni & 1) * 2];
                    const uint32_t b1r = bf[ni >> 1][(ni & 1) * 2 + 1];
                    MMA16816(acc[0][ni], af[0], b0r, b1r);
                    MMA16816(acc[1][ni], af[1], b0r, b1r);
                }
            }
        }

        {
            const float* bs = (const float*)(sm + BIAS_OFF) + kg * C_OUTX;
#pragma unroll
            for (int mi = 0; mi < 2; ++mi) {
                const int v1 = v0 + warp_m * 32 + mi * 16 + rr;
                const int v2 = v1 + 8;
                uint32_t pk1[8], pk2[8];
#pragma unroll
                for (int ni = 0; ni < 8; ++ni) {
                    const int n = warp_n * 64 + ni * 8 + qq * 2;
                    const float b0v = bs[n], b1v = bs[n + 1];
                    pk1[ni] = h2pack(acc[mi][ni][0] + b0v, acc[mi][ni][1] + b1v);
                    pk2[ni] = h2pack(acc[mi][ni][2] + b0v, acc[mi][ni][3] + b1v);
                    acc[mi][ni][0] = 0.0f; acc[mi][ni][1] = 0.0f;
                    acc[mi][ni][2] = 0.0f; acc[mi][ni][3] = 0.0f;
                }
                if (v1 < N_LOW) {
                    char* row = (char*)(g_y + ((size_t)(v1 * KNEIGH + kg) * BB + b) * C_OUTX);
                    __stcs((uint4*)(row + warp_n * 128 + qq * 16),      make_uint4(pk1[0], pk1[1], pk1[2], pk1[3]));
                    __stcs((uint4*)(row + warp_n * 128 + 64 + qq * 16), make_uint4(pk1[4], pk1[5], pk1[6], pk1[7]));
                }
                if (v2 < N_LOW) {
                    char* row = (char*)(g_y + ((size_t)(v2 * KNEIGH + kg) * BB + b) * C_OUTX);
                    __stcs((uint4*)(row + warp_n * 128 + qq * 16),      make_uint4(pk2[0], pk2[1], pk2[2], pk2[3]));
                    __stcs((uint4*)(row + warp_n * 128 + 64 + qq * 16), make_uint4(pk2[4], pk2[5], pk2[6], pk2[7]));
                }
            }
        }
    }

    __threadfence();
    __syncthreads();
    if (tid == 0) atomicAdd(&g_done[b], 1);
}

// one gather job: 32 up-vertices x one batch
__device__ void do_gather(int job, float* __restrict__ out, char* sm) {
    float* ts = (float*)sm;
    const int tid  = threadIdx.x;
    const int wid  = tid >> 5;
    const int lane = tid & 31;
    const int b    = job / GBLK;
    const int u0   = (job % GBLK) * 32;

    if (tid == 0) {
        while (atomicAdd(&g_ready, 0) == 0) __nanosleep(256);
        while (atomicAdd(&g_done[b], 0) < VTILES) __nanosleep(256);
        __threadfence();
    }
    __syncthreads();

    const int N0 = (lane >> 4) * 64
                 + (((lane >> 3) & 1) * 4 + 2 * (lane & 1)) * 8
                 + ((lane >> 1) & 3) * 2;

#pragma unroll
    for (int k = 0; k < 4; ++k) {
        const int uu = wid * 4 + k;
        const int u  = u0 + uu;
        float4 a = make_float4(0.f, 0.f, 0.f, 0.f);
        if (u < N_UP) {
            const int s = g_off[u], e = g_off[u + 1];
            const float inv = g_inv[u];
            for (int j = s; j < e; ++j) {
                const int f = g_csr[j];
                const float2 rv = __ldcs((const float2*)(g_y + ((size_t)f * BB + b) * C_OUTX) + lane);
                const float2 p0 = __half22float2(*(const __half2*)&rv.x);
                const float2 p1 = __half22float2(*(const __half2*)&rv.y);
                a.x += p0.x; a.y += p0.y; a.z += p1.x; a.w += p1.y;
            }
            a.x *= inv; a.y *= inv; a.z *= inv; a.w *= inv;
        }
        ts[(N0 + 0) * 33 + uu] = a.x;
        ts[(N0 + 1) * 33 + uu] = a.y;
        ts[(N0 + 8) * 33 + uu] = a.z;
        ts[(N0 + 9) * 33 + uu] = a.w;
    }
    __syncthreads();

    float* ob = out + (size_t)b * C_OUTX * N_UP;
    const bool full = (u0 + 32) <= N_UP;
#pragma unroll
    for (int i = 0; i < 8; ++i) {
        const int idx = i * 256 + tid;
        const int n   = idx >> 4;
        const int seg = idx & 15;
        const int u   = u0 + seg * 2;
        const float w0 = ts[n * 33 + seg * 2];
        const float w1 = ts[n * 33 + seg * 2 + 1];
        if (full) {
            __stcs((float2*)(ob + (size_t)n * N_UP + u), make_float2(w0, w1));
        } else {
            if (u < N_UP)     ob[(size_t)n * N_UP + u]     = w0;
            if (u + 1 < N_UP) ob[(size_t)n * N_UP + u + 1] = w1;
        }
    }
}

// ticket -> job: ALL gemm tiles first (batch-major), then ALL gathers (batch-major).
// Gemm runs full-width; freed CTAs tail-fill with gathers for long-finished batches.
__device__ __forceinline__ void decode(int p, int& type, int& job) {
    if (p < NTILES) { type = 0; job = p; }
    else            { type = 1; job = p - NTILES; }
}

__global__ __launch_bounds__(NTH, 2)
void mega_k(const float* __restrict__ x,
            const float* __restrict__ bias,
            const int*   __restrict__ neigh,
            float*       __restrict__ out)
{
    extern __shared__ __align__(128) char sm[];
    const uint32_t sb = smem_u32(sm);
    const int tid = threadIdx.x;
    __shared__ int smT;

    for (int i = tid; i < KF; i += NTH)
        ((float*)(sm + BIAS_OFF))[i] = bias[i];

    if (blockIdx.x < NCSR) csr_build(neigh, blockIdx.x);

    for (;;) {
        if (tid == 0) smT = (int)atomicAdd(&g_ticket, 1u);
        __syncthreads();
        const int p = smT;
        if (p >= NT_TOTAL) break;
        int type, job;
        decode(p, type, job);
        if (type == 0) do_tile(job, x, sm, sb);
        else           do_gather(job, out, sm);
    }
}

// ---------------- launch ----------------
extern "C" void kernel_launch(void* const* d_in, const int* in_sizes, int n_in,
                              void* d_out, int out_size)
{
    const float* x     = (const float*)d_in[0];   // [16,256,10242]
    const float* w     = (const float*)d_in[1];   // [256,896]
    const float* bias  = (const float*)d_in[2];   // [896]
    const int*   neigh = (const int*)  d_in[3];   // [71694]
    float*       out   = (float*)d_out;           // [16,128,40962]

    static int nsm = 0;
    if (!nsm) {
        cudaDeviceGetAttribute(&nsm, cudaDevAttrMultiProcessorCount, 0);
        if (nsm <= 0) nsm = 148;
        cudaFuncSetAttribute(mega_k,
                             cudaFuncAttributeMaxDynamicSharedMemorySize,
                             (int)SMEM_ALLOC);
    }

    reset_k<<<1, 32>>>();
    prep_w_k<<<(KNEIGH * 4 * 128 * 64 + 255) / 256, 256>>>(w);
    mega_k<<<nsm * 2, NTH, SMEM_ALLOC>>>(x, bias, neigh, out);
}

// round 17
// speedup vs baseline: 1.6642x; 1.6642x over previous
#include <cuda_runtime.h>
#include <cuda_fp16.h>
#include <cstdint>

// ---------------- problem constants ----------------
#define BB      16
#define C_OUTX  128
#define C_INX   256
#define N_LOW   10242
#define N_UP    40962
#define KNEIGH  7
#define KF      896               // KNEIGH * C_OUTX
#define NFLAT   (N_LOW * KNEIGH)  // 71694
#define TM      128
#define NTH     256
#define VTILES  81

// ---------------- SMEM layout ----------------
#define A_OFF    0
#define A_STRIDE 528
#define A_BYTES  (128 * A_STRIDE)       // 67584
#define B_OFF    A_BYTES
#define B_STRIDE 144
#define B_BUF    (128 * B_STRIDE)       // 18432
#define BIAS_OFF (B_OFF + 2 * B_BUF)    // 104448
#define SMEM_ALLOC (BIAS_OFF + KF * 4)  // 108032

#define SCAN_NB  ((N_UP + 255) / 256)   // 161
#define WPACK_N  (KNEIGH * 4 * 128 * 64)  // 229376

// ---------------- device scratch ----------------
__device__ int   g_cnt[N_UP];
__device__ int   g_off[N_UP + 1];
__device__ int   g_pos[N_UP];
__device__ int   g_csr[NFLAT];
__device__ float g_inv[N_UP];
__device__ int   g_bsum[SCAN_NB];
__device__ int   g_bbase[SCAN_NB];
// W fp16, packed [kg][kchunk][n 128][k 64]
__device__ __half g_wpack[WPACK_N];
// dense intermediate y[f][b][pi(n)] fp16, f = v*7+kg  (n permuted)
__device__ __half g_y[(size_t)NFLAT * BB * C_OUTX];

// ---------------- PTX helpers (plain sm_80+) ----------------
__device__ __forceinline__ uint32_t smem_u32(const void* p) {
    uint32_t a;
    asm("{ .reg .u64 t; cvta.to.shared.u64 t, %1; cvt.u32.u64 %0, t; }" : "=r"(a) : "l"(p));
    return a;
}
#define LDSM4(r, addr) \
    asm volatile("ldmatrix.sync.aligned.m8n8.x4.shared.b16 {%0,%1,%2,%3}, [%4];" \
        : "=r"((r)[0]), "=r"((r)[1]), "=r"((r)[2]), "=r"((r)[3]) : "r"(addr))
#define MMA16816(d, a, b0, b1) \
    asm volatile("mma.sync.aligned.m16n8k16.row.col.f32.f16.f16.f32 " \
        "{%0,%1,%2,%3}, {%4,%5,%6,%7}, {%8,%9}, {%0,%1,%2,%3};" \
        : "+f"((d)[0]), "+f"((d)[1]), "+f"((d)[2]), "+f"((d)[3]) \
        : "r"((a)[0]), "r"((a)[1]), "r"((a)[2]), "r"((a)[3]), "r"(b0), "r"(b1))
#define CP16(dst, src) \
    asm volatile("cp.async.cg.shared.global [%0], [%1], 16;" :: "r"(dst), "l"(src))
#define CP_COMMIT() asm volatile("cp.async.commit_group;")
#define CP_WAIT0()  asm volatile("cp.async.wait_group 0;")

__device__ __forceinline__ uint32_t h2pack(float a, float b) {
    __half2 h = __floats2half2_rn(a, b);
    return *(uint32_t*)&h;
}

// ---------------- prep kernels ----------------
// fused: zero counts + pack W (disjoint outputs, no ordering needed)
__global__ void prep0_k(const float* __restrict__ w) {
    int idx = blockIdx.x * blockDim.x + threadIdx.x;
    if (idx < N_UP) { g_cnt[idx] = 0; g_pos[idx] = 0; }
    if (idx < WPACK_N) {
        int kk = idx & 63;
        int n  = (idx >> 6) & 127;
        int c  = (idx >> 13) & 3;
        int kg = idx >> 15;
        float v = w[(size_t)(c * 64 + kk) * KF + kg * C_OUTX + n];
        g_wpack[(size_t)(kg * 4 + c) * 8192 + n * 64 + kk] = __float2half_rn(v);
    }
}
__global__ void count_k(const int* __restrict__ neigh) {
    int i = blockIdx.x * blockDim.x + threadIdx.x;
    if (i < NFLAT) atomicAdd(&g_cnt[neigh[i]], 1);
}

// ---- 3-stage block scan of g_cnt -> g_off (exclusive); also g_inv ----
__global__ __launch_bounds__(256) void scan_sum_k() {
    const int tid = threadIdx.x;
    const int i = blockIdx.x * 256 + tid;
    int v = (i < N_UP) ? g_cnt[i] : 0;
#pragma unroll
    for (int d = 16; d > 0; d >>= 1) v += __shfl_down_sync(0xFFFFFFFFu, v, d);
    __shared__ int ws[8];
    if ((tid & 31) == 0) ws[tid >> 5] = v;
    __syncthreads();
    if (tid == 0) {
        int s = 0;
#pragma unroll
        for (int j = 0; j < 8; ++j) s += ws[j];
        g_bsum[blockIdx.x] = s;
    }
}
__global__ __launch_bounds__(256) void scan_base_k() {
    const int tid = threadIdx.x;
    int v = (tid < SCAN_NB) ? g_bsum[tid] : 0;
    int s = v;
#pragma unroll
    for (int d = 1; d < 32; d <<= 1) {
        int t = __shfl_up_sync(0xFFFFFFFFu, s, d);
        if ((tid & 31) >= d) s += t;
    }
    __shared__ int ws[8];
    if ((tid & 31) == 31) ws[tid >> 5] = s;
    __syncthreads();
    if (tid < 32) {
        int w = (tid < 8) ? ws[tid] : 0;
#pragma unroll
        for (int d = 1; d < 8; d <<= 1) {
            int t = __shfl_up_sync(0xFFFFFFFFu, w, d);
            if (tid >= d) w += t;
        }
        if (tid < 8) ws[tid] = w;
    }
    __syncthreads();
    int incl = s + ((tid >= 32) ? ws[(tid >> 5) - 1] : 0);
    if (tid < SCAN_NB) g_bbase[tid] = incl - v;   // exclusive base
    if (tid == 0) g_off[N_UP] = NFLAT;
}
__global__ __launch_bounds__(256) void scan_fill_k() {
    const int tid = threadIdx.x;
    const int i = blockIdx.x * 256 + tid;
    int v = (i < N_UP) ? g_cnt[i] : 0;
    int s = v;
#pragma unroll
    for (int d = 1; d < 32; d <<= 1) {
        int t = __shfl_up_sync(0xFFFFFFFFu, s, d);
        if ((tid & 31) >= d) s += t;
    }
    __shared__ int ws[8];
    if ((tid & 31) == 31) ws[tid >> 5] = s;
    __syncthreads();
    if (tid < 32) {
        int w = (tid < 8) ? ws[tid] : 0;
#pragma unroll
        for (int d = 1; d < 8; d <<= 1) {
            int t = __shfl_up_sync(0xFFFFFFFFu, w, d);
            if (tid >= d) w += t;
        }
        if (tid < 8) ws[tid] = w;
    }
    __syncthreads();
    int excl = s - v + ((tid >= 32) ? ws[(tid >> 5) - 1] : 0);
    if (i < N_UP) {
        g_off[i] = g_bbase[blockIdx.x] + excl;
        g_inv[i] = 1.0f / (float)v;
    }
}

__global__ void fill_k(const int* __restrict__ neigh) {
    int i = blockIdx.x * blockDim.x + threadIdx.x;
    if (i < NFLAT) {
        int u = neigh[i];
        int slot = atomicAdd(&g_pos[u], 1);
        g_csr[g_off[u] + slot] = i;
    }
}

// ---------------- phase 1: fp16 HMMA GEMM -> y (fp16, permuted n) ----------------
__device__ __forceinline__ void issue_chunk(uint32_t sb, int tid, int t, int buf) {
    const __half* src = g_wpack + (size_t)t * 8192;
    uint32_t dst = sb + B_OFF + buf * B_BUF;
#pragma unroll
    for (int o = 0; o < 4; ++o) {
        int flat = o * NTH + tid;          // 0..1023 x 16B
        int n   = flat >> 3;
        int seg = flat & 7;
        CP16(dst + n * B_STRIDE + seg * 16, (const char*)src + n * 128 + seg * 16);
    }
}

__global__ __launch_bounds__(NTH, 2)
void gemm_k(const float* __restrict__ x,
            const float* __restrict__ bias)
{
    extern __shared__ __align__(128) char sm[];
    const uint32_t sb = smem_u32(sm);

    const int tid    = threadIdx.x;
    const int wid    = tid >> 5;
    const int lane   = tid & 31;
    const int warp_m = wid & 3;       // 32-row group
    const int warp_n = wid >> 2;      // 64-col group
    const int v0     = blockIdx.x * TM;
    const int b      = blockIdx.y;

    // ---- stage A: x -> fp16, row-major [m][k], padded stride ----
    {
        const float* xb = x + (size_t)b * C_INX * N_LOW;
        const int v = tid & 127;
        const int cstart = (tid >> 7) * 2;     // 0 or 2
        const bool valid = (v0 + v) < N_LOW;
        for (int c = cstart; c < C_INX; c += 4) {
            float f0 = valid ? __ldcs(xb + (size_t)c * N_LOW + v0 + v) : 0.0f;
            float f1 = valid ? __ldcs(xb + (size_t)(c + 1) * N_LOW + v0 + v) : 0.0f;
            *(__half2*)(sm + A_OFF + v * A_STRIDE + c * 2) = __floats2half2_rn(f0, f1);
        }
    }
    for (int i = tid; i < KF; i += NTH)
        ((float*)(sm + BIAS_OFF))[i] = bias[i];
    __syncthreads();

    const uint32_t aB = sb + A_OFF + (warp_m * 32 + (lane & 15)) * A_STRIDE + (lane >> 4) * 16;
    const uint32_t brOff = (uint32_t)(warp_n * 64 + (lane & 7) + ((lane >> 4) & 1) * 8) * B_STRIDE
                         + ((lane >> 3) & 1) * 16;

    float acc[2][8][4];
#pragma unroll
    for (int mi = 0; mi < 2; ++mi)
#pragma unroll
        for (int ni = 0; ni < 8; ++ni)
#pragma unroll
            for (int q = 0; q < 4; ++q) acc[mi][ni][q] = 0.0f;

    issue_chunk(sb, tid, 0, 0);
    CP_COMMIT();

    const int qq = lane & 3;       // fragment column quad
    const int rr = lane >> 2;      // fragment row within 8

    for (int kg = 0; kg < KNEIGH; ++kg) {
#pragma unroll
        for (int c = 0; c < 4; ++c) {
            const int t = kg * 4 + c;
            CP_WAIT0();
            __syncthreads();   // chunk t visible; reads of other buffer retired
            if (t + 1 < 28) { issue_chunk(sb, tid, t + 1, (t + 1) & 1); CP_COMMIT(); }

            const uint32_t bB = sb + B_OFF + (t & 1) * B_BUF + brOff;
            const int cByte = c * 128;

            // warp phase rotation: warp 'wid' processes k-substeps in order
            // (wid, wid+1, wid+2, wid+3) mod 4 — breaks the LDSM/MMA convoy
            // (K-accumulation order is commutative, so result is unchanged).
#pragma unroll
            for (int s = 0; s < 4; ++s) {
                const int se = (s + wid) & 3;
                const int kb = cByte + se * 32;
                uint32_t af[2][4], bf[4][4];
                LDSM4(af[0], aB + kb);
                LDSM4(af[1], aB + 16 * A_STRIDE + kb);
#pragma unroll
                for (int p = 0; p < 4; ++p)
                    LDSM4(bf[p], bB + p * (16 * B_STRIDE) + se * 32);
#pragma unroll
                for (int ni = 0; ni < 8; ++ni) {
                    const uint32_t b0r = bf[ni >> 1][(ni & 1) * 2];
                    const uint32_t b1r = bf[ni >> 1][(ni & 1) * 2 + 1];
                    MMA16816(acc[0][ni], af[0], b0r, b1r);
                    MMA16816(acc[1][ni], af[1], b0r, b1r);
                }
            }
        }

        // ---- write y (fp16, permuted n) for this kg; coalesced STG.128 ----
        {
            const float* bs = (const float*)(sm + BIAS_OFF) + kg * C_OUTX;
#pragma unroll
            for (int mi = 0; mi < 2; ++mi) {
                const int v1 = v0 + warp_m * 32 + mi * 16 + rr;
                const int v2 = v1 + 8;
                uint32_t pk1[8], pk2[8];
#pragma unroll
                for (int ni = 0; ni < 8; ++ni) {
                    const int n = warp_n * 64 + ni * 8 + qq * 2;
                    const float b0v = bs[n], b1v = bs[n + 1];
                    pk1[ni] = h2pack(acc[mi][ni][0] + b0v, acc[mi][ni][1] + b1v);
                    pk2[ni] = h2pack(acc[mi][ni][2] + b0v, acc[mi][ni][3] + b1v);
                    acc[mi][ni][0] = 0.0f; acc[mi][ni][1] = 0.0f;
                    acc[mi][ni][2] = 0.0f; acc[mi][ni][3] = 0.0f;
                }
                if (v1 < N_LOW) {
                    char* row = (char*)(g_y + ((size_t)(v1 * KNEIGH + kg) * BB + b) * C_OUTX);
                    __stcs((uint4*)(row + warp_n * 128 + qq * 16),      make_uint4(pk1[0], pk1[1], pk1[2], pk1[3]));
                    __stcs((uint4*)(row + warp_n * 128 + 64 + qq * 16), make_uint4(pk1[4], pk1[5], pk1[6], pk1[7]));
                }
                if (v2 < N_LOW) {
                    char* row = (char*)(g_y + ((size_t)(v2 * KNEIGH + kg) * BB + b) * C_OUTX);
                    __stcs((uint4*)(row + warp_n * 128 + qq * 16),      make_uint4(pk2[0], pk2[1], pk2[2], pk2[3]));
                    __stcs((uint4*)(row + warp_n * 128 + 64 + qq * 16), make_uint4(pk2[4], pk2[5], pk2[6], pk2[7]));
                }
            }
        }
    }
}

// ---------------- phase 2: CSR gather -> out ----------------
__global__ __launch_bounds__(256)
void gather_k(float* __restrict__ out)
{
    __shared__ float ts[128 * 33];
    const int tid  = threadIdx.x;
    const int wid  = tid >> 5;
    const int lane = tid & 31;
    const int u0   = blockIdx.x * 32;
    const int b    = blockIdx.y;

    // un-permute: lane reads halves P = 4*lane .. 4*lane+3 of a y row
    //   -> true n = N0, N0+1, N0+8, N0+9
    const int N0 = (lane >> 4) * 64
                 + (((lane >> 3) & 1) * 4 + 2 * (lane & 1)) * 8
                 + ((lane >> 1) & 3) * 2;

#pragma unroll
    for (int k = 0; k < 4; ++k) {
        const int uu = wid * 4 + k;
        const int u  = u0 + uu;
        float4 a = make_float4(0.f, 0.f, 0.f, 0.f);
        if (u < N_UP) {
            const int s = g_off[u], e = g_off[u + 1];
            const float inv = g_inv[u];
            for (int j = s; j < e; ++j) {
                const int f = g_csr[j];
                const float2 rv = __ldcs((const float2*)(g_y + ((size_t)f * BB + b) * C_OUTX) + lane);
                const float2 p0 = __half22float2(*(const __half2*)&rv.x);
                const float2 p1 = __half22float2(*(const __half2*)&rv.y);
                a.x += p0.x; a.y += p0.y; a.z += p1.x; a.w += p1.y;
            }
            a.x *= inv; a.y *= inv; a.z *= inv; a.w *= inv;
        }
        ts[(N0 + 0) * 33 + uu] = a.x;
        ts[(N0 + 1) * 33 + uu] = a.y;
        ts[(N0 + 8) * 33 + uu] = a.z;
        ts[(N0 + 9) * 33 + uu] = a.w;
    }
    __syncthreads();

    float* ob = out + (size_t)b * C_OUTX * N_UP;
    const bool full = (u0 + 32) <= N_UP;
#pragma unroll
    for (int i = 0; i < 8; ++i) {
        const int idx = i * 256 + tid;     // 2048 float2
        const int n   = idx >> 4;
        const int seg = idx & 15;
        const int u   = u0 + seg * 2;
        const float w0 = ts[n * 33 + seg * 2];
        const float w1 = ts[n * 33 + seg * 2 + 1];
        if (full) {
            __stcs((float2*)(ob + (size_t)n * N_UP + u), make_float2(w0, w1));
        } else {
            if (u < N_UP)     ob[(size_t)n * N_UP + u]     = w0;
            if (u + 1 < N_UP) ob[(size_t)n * N_UP + u + 1] = w1;
        }
    }
}

// ---------------- launch: single stream, discrete kernels ----------------
extern "C" void kernel_launch(void* const* d_in, const int* in_sizes, int n_in,
                              void* d_out, int out_size)
{
    const float* x     = (const float*)d_in[0];   // [16,256,10242]
    const float* w     = (const float*)d_in[1];   // [256,896]
    const float* bias  = (const float*)d_in[2];   // [896]
    const int*   neigh = (const int*)  d_in[3];   // [71694]
    float*       out   = (float*)d_out;           // [16,128,40962]

    static bool attr_set = false;
    if (!attr_set) {
        cudaFuncSetAttribute(gemm_k,
                             cudaFuncAttributeMaxDynamicSharedMemorySize,
                             (int)SMEM_ALLOC);
        attr_set = true;
    }

    prep0_k<<<(WPACK_N + 255) / 256, 256>>>(w);       // zero counts + pack W
    count_k<<<(NFLAT + 255) / 256, 256>>>(neigh);
    scan_sum_k<<<SCAN_NB, 256>>>();
    scan_base_k<<<1, 256>>>();
    scan_fill_k<<<SCAN_NB, 256>>>();
    fill_k<<<(NFLAT + 255) / 256, 256>>>(neigh);

    dim3 grid1(VTILES, BB);
    gemm_k<<<grid1, NTH, SMEM_ALLOC>>>(x, bias);

    dim3 grid2((N_UP + 31) / 32, BB);
    gather_k<<<grid2, 256>>>(out);
}